// round 11
// baseline (speedup 1.0000x reference)
#include <cuda_runtime.h>
#include <math.h>
#include <stdint.h>

typedef unsigned long long ull;

#define SEQ   1024
#define BATCH 64
#define DH    256
#define DIN   256
#define NBLK  128
#define NTHR  256

// ---------------- device scratch (static allocs only) -----------------------
__device__ float    g_xq[(size_t)SEQ * 1024 * 64];   // [t][gatecol][b], 256MB
__device__ float    g_hbuf[2][DH * BATCH];           // double-buffered h, [unit][batch]
__device__ unsigned g_pflag[(SEQ + 1) * NBLK];       // per-step, per-CTA flags (4B packed)

// ---------------- f32x2 packed helpers (Blackwell) --------------------------
__device__ __forceinline__ ull fma2(ull a, ull b, ull c) {
    ull d;
    asm("fma.rn.f32x2 %0, %1, %2, %3;" : "=l"(d) : "l"(a), "l"(b), "l"(c));
    return d;
}
__device__ __forceinline__ ull add2(ull a, ull b) {
    ull d;
    asm("add.rn.f32x2 %0, %1, %2;" : "=l"(d) : "l"(a), "l"(b));
    return d;
}
__device__ __forceinline__ ull pack2(float x, float y) {
    ull r;
    asm("mov.b64 %0, {%1, %2};" : "=l"(r) : "f"(x), "f"(y));
    return r;
}
__device__ __forceinline__ float2 unpack2(ull v) {
    float2 r;
    asm("mov.b64 {%0, %1}, %2;" : "=f"(r.x), "=f"(r.y) : "l"(v));
    return r;
}
__device__ __forceinline__ ull ldcg_u64(const void* p) {
    ull v;
    asm volatile("ld.global.cg.u64 %0, [%1];" : "=l"(v) : "l"(p));
    return v;
}
__device__ __forceinline__ unsigned ld_acq(const unsigned* p) {
    unsigned v;
    asm volatile("ld.acquire.gpu.global.u32 %0, [%1];" : "=r"(v) : "l"(p));
    return v;
}
__device__ __forceinline__ void st_rel(unsigned* p, unsigned v) {
    asm volatile("st.release.gpu.global.u32 [%0], %1;" :: "l"(p), "r"(v) : "memory");
}
// fast tanh: 1 - 2/(exp(2x)+1)
__device__ __forceinline__ float ftanh(float x) {
    float e = __expf(2.0f * x);
    return 1.0f - 2.0f / (e + 1.0f);
}
__device__ __forceinline__ float fsigmoid(float x) {
    return 1.0f / (1.0f + __expf(-x));
}

// ======================= Phase 1: X projection GEMM =========================
__global__ __launch_bounds__(256) void xproj_kernel(
    const float* __restrict__ X,
    const float* __restrict__ Wf, const float* __restrict__ Wi,
    const float* __restrict__ Wg, const float* __restrict__ Wo,
    const float* __restrict__ bf, const float* __restrict__ bi,
    const float* __restrict__ bg, const float* __restrict__ bo)
{
    __shared__ float As[16 * 68];   // [k][row]
    __shared__ float Bs[16 * 68];   // [k][col]

    const int t    = blockIdx.y;
    const int bx   = blockIdx.x;           // 0..15
    const int gsel = bx >> 2;
    const int j0   = (bx & 3) * 64;
    const float* W    = (gsel == 0) ? Wf : (gsel == 1) ? Wi : (gsel == 2) ? Wg : Wo;
    const float* bias = (gsel == 0) ? bf : (gsel == 1) ? bi : (gsel == 2) ? bg : bo;

    const int tx = threadIdx.x;

    // re-zero flags every replay (xproj completes before lstm starts)
    if (bx == 0 && tx < 128) {
        g_pflag[t * NBLK + tx] = 0u;
        if (t == 0) g_pflag[SEQ * NBLK + tx] = 0u;
    }

    const int trow4 = (tx >> 4) * 4;
    const int tcol4 = (tx & 15) * 4;

    const int arow = tx >> 2;
    const int akq  = (tx & 3) * 4;
    const int bk   = tx >> 4;
    const int bc4  = (tx & 15) * 4;

    const float* Aptr = X + ((size_t)t * 64 + arow) * 256 + akq;
    const float* Bptr = W + (size_t)bk * 256 + j0 + bc4;

    ull acc[8];
    #pragma unroll
    for (int i = 0; i < 8; ++i) acc[i] = 0ull;

    float4 aReg = *(const float4*)Aptr;
    float4 bReg = *(const float4*)Bptr;

    for (int kt = 0; kt < 16; ++kt) {
        __syncthreads();
        As[(akq + 0) * 68 + arow] = aReg.x;
        As[(akq + 1) * 68 + arow] = aReg.y;
        As[(akq + 2) * 68 + arow] = aReg.z;
        As[(akq + 3) * 68 + arow] = aReg.w;
        *(float4*)&Bs[bk * 68 + bc4] = bReg;
        if (kt < 15) {
            aReg = *(const float4*)(Aptr + (kt + 1) * 16);
            bReg = *(const float4*)(Bptr + (size_t)(kt + 1) * 16 * 256);
        }
        __syncthreads();

        #pragma unroll
        for (int k = 0; k < 16; ++k) {
            float4 a4 = *(const float4*)&As[k * 68 + trow4];
            float4 b4 = *(const float4*)&Bs[k * 68 + tcol4];
            ull a01 = pack2(a4.x, a4.y);
            ull a23 = pack2(a4.z, a4.w);
            ull bb;
            bb = pack2(b4.x, b4.x); acc[0] = fma2(a01, bb, acc[0]); acc[1] = fma2(a23, bb, acc[1]);
            bb = pack2(b4.y, b4.y); acc[2] = fma2(a01, bb, acc[2]); acc[3] = fma2(a23, bb, acc[3]);
            bb = pack2(b4.z, b4.z); acc[4] = fma2(a01, bb, acc[4]); acc[5] = fma2(a23, bb, acc[5]);
            bb = pack2(b4.w, b4.w); acc[6] = fma2(a01, bb, acc[6]); acc[7] = fma2(a23, bb, acc[7]);
        }
    }

    #pragma unroll
    for (int jj = 0; jj < 4; ++jj) {
        float bv = bias[j0 + tcol4 + jj];
        float2 p01 = unpack2(acc[2 * jj]);
        float2 p23 = unpack2(acc[2 * jj + 1]);
        float4 outv = make_float4(p01.x + bv, p01.y + bv, p23.x + bv, p23.y + bv);
        size_t c = (size_t)bx * 64 + tcol4 + jj;
        *(float4*)&g_xq[(size_t)t * 65536 + c * 64 + trow4] = outv;
    }
}

// ======================= Phase 2: persistent recurrence =====================
// 128 CTAs x 256 thr. CTA owns 2 hidden units (8 gate-cols c = g*2+uu).
// Warp kc consumes h units [kc*32, kc*32+32) from CTA group kc (16 CTAs);
// it polls the group's 16 per-CTA release flags with ONE coalesced 64B
// acquire-load + all-vote + backoff. Fused reduce+update in warps 0-1 (no
// gate_s, one full sync/step); pp(t)read-vs-pp(t+1)store guarded by split
// named barrier 2 (warps 0-1 arrive, warps 2-7 sync).
__global__ __launch_bounds__(NTHR, 1) void lstm_seq_kernel(
    const float* __restrict__ Wf, const float* __restrict__ Wi,
    const float* __restrict__ Wg, const float* __restrict__ Wo,
    float* __restrict__ out)
{
    __shared__ ull wh2[2048];      // [k][8c] dup pairs, 16KB
    __shared__ ull pp[2048];       // [8 kc][8 c][32 bp] partials, 16KB
    __shared__ ull c_s[64];        // [2 u][32 bp]

    const int tx   = threadIdx.x;
    const int bx   = blockIdx.x;
    const int u0   = bx << 1;
    const int kc   = tx >> 5;      // warp id = k-chunk (32 k each)
    const int lane = tx & 31;      // batch-pair

    // ---- load Wh slice (rows 256..511), duplicated pairs wh2[k*8 + c] ----
    for (int idx = tx; idx < 2048; idx += NTHR) {
        int k = idx >> 3, c = idx & 7;
        const float* W = (c < 4) ? ((c < 2) ? Wf : Wi) : ((c < 6) ? Wg : Wo);
        float w = W[(size_t)(256 + k) * 256 + u0 + (c & 1)];
        wh2[idx] = pack2(w, w);
    }

    // ---- init h(0)=0, c=0 ----
    if (tx < 64) {
        c_s[tx] = 0ull;
        int u = tx >> 5, bp = tx & 31;
        *(ull*)&g_hbuf[0][(u0 + u) * 64 + (bp << 1)] = 0ull;
    }
    __syncthreads();
    if (tx == 0) st_rel(&g_pflag[bx], 1u);

    // warps 0-1 pre-arrive phase 0 of barrier 2 (no pp reads before t=0)
    if (tx < 64) asm volatile("bar.arrive 2, %0;" :: "r"(NTHR) : "memory");

    float* outs = out;
    float* hxo  = out + (size_t)SEQ * 64 * 256;
    float* cxo  = hxo + 64 * 256;

    const ull* wbase = wh2 + (kc << 8);
    const int  u_    = tx >> 5;        // (valid when tx<64)
    const int  bp_   = tx & 31;

    for (int t = 0; t < SEQ; ++t) {
        // prefetch x-projection for the 4 gates of my (u,bp)  [tx<64 only]
        ull xq4[4];
        if (tx < 64) {
            #pragma unroll
            for (int g = 0; g < 4; ++g)
                xq4[g] = *(const ull*)&g_xq[(size_t)t * 65536 +
                        (size_t)(g * 256 + u0 + u_) * 64 + (bp_ << 1)];
        }

        // per-warp wait: one coalesced 64B acquire-load of my group's flags
        {
            const unsigned* fp = &g_pflag[t * NBLK + (kc << 4) + (lane & 15)];
            unsigned v = ld_acq(fp);
            while (!__all_sync(0xffffffffu, v != 0u)) {
                __nanosleep(30);
                v = ld_acq(fp);
            }
        }

        // ---- GEMM: acc[c] += sum over 32 k of h[kc*32+k][2lane..] * w[k][c] ----
        const float* hb = g_hbuf[t & 1] + (kc << 11) + (lane << 1);
        ull acc[8];
        #pragma unroll
        for (int i = 0; i < 8; ++i) acc[i] = 0ull;
        #pragma unroll 8
        for (int k = 0; k < 32; ++k) {
            ull hh = ldcg_u64(hb + (k << 6));
            const ulonglong2* wv = (const ulonglong2*)(wbase + (k << 3));
            ulonglong2 w01 = wv[0], w23 = wv[1], w45 = wv[2], w67 = wv[3];
            acc[0] = fma2(hh, w01.x, acc[0]); acc[1] = fma2(hh, w01.y, acc[1]);
            acc[2] = fma2(hh, w23.x, acc[2]); acc[3] = fma2(hh, w23.y, acc[3]);
            acc[4] = fma2(hh, w45.x, acc[4]); acc[5] = fma2(hh, w45.y, acc[5]);
            acc[6] = fma2(hh, w67.x, acc[6]); acc[7] = fma2(hh, w67.y, acc[7]);
        }

        // warps 2-7: wait until warps 0-1 finished reading pp(t-1)
        if (tx >= 64) asm volatile("bar.sync 2, %0;" :: "r"(NTHR) : "memory");
        {
            ull* pdst = pp + (kc << 8) + lane;
            #pragma unroll
            for (int c = 0; c < 8; ++c) pdst[c << 5] = acc[c];
        }
        __syncthreads();                         // pp(t) ready CTA-wide

        // ---- fused reduce + activation + state update (warps 0-1) ----
        if (tx < 64) {
            ull s[4];
            #pragma unroll
            for (int g = 0; g < 4; ++g) {
                const ull* q = pp + (((g << 1) + u_) << 5) + bp_;
                ull a0 = add2(q[0],    q[256]);
                ull a1 = add2(q[512],  q[768]);
                ull a2 = add2(q[1024], q[1280]);
                ull a3 = add2(q[1536], q[1792]);
                s[g] = add2(add2(add2(a0, a1), add2(a2, a3)), xq4[g]);
            }
            // pp reads done -> let warps 2-7 start storing pp(t+1)
            if (t < SEQ - 1) asm volatile("bar.arrive 2, %0;" :: "r"(NTHR) : "memory");

            float2 vf = unpack2(s[0]), vi = unpack2(s[1]);
            float2 vg = unpack2(s[2]), vo = unpack2(s[3]);
            float fx = fsigmoid(vf.x), fy = fsigmoid(vf.y);
            float ix = fsigmoid(vi.x), iy = fsigmoid(vi.y);
            float gx = ftanh(vg.x),    gy = ftanh(vg.y);
            float ox = fsigmoid(vo.x), oy = fsigmoid(vo.y);
            float2 co = unpack2(c_s[tx]);
            float c0 = fx * co.x + ix * gx;
            float c1 = fy * co.y + iy * gy;
            c_s[tx] = pack2(c0, c1);
            float h0 = ox * ftanh(c0);
            float h1 = oy * ftanh(c1);
            int j = u0 + u_;
            int b = bp_ << 1;
            *(ull*)&g_hbuf[(t + 1) & 1][j * 64 + b] = pack2(h0, h1);
            asm volatile("bar.sync 1, 64;" ::: "memory");   // warps 0-1 only
            if (tx == 0) st_rel(&g_pflag[(t + 1) * NBLK + bx], 1u);
            outs[((size_t)t * 64 + b) * 256 + j]     = h0;
            outs[((size_t)t * 64 + b + 1) * 256 + j] = h1;
            if (t == SEQ - 1) {
                hxo[b * 256 + j] = h0; hxo[(b + 1) * 256 + j] = h1;
                cxo[b * 256 + j] = c0; cxo[(b + 1) * 256 + j] = c1;
            }
        }
        // warps 2-7 proceed directly to next step's poll
    }
}

// ============================== launch ======================================
extern "C" void kernel_launch(void* const* d_in, const int* in_sizes, int n_in,
                              void* d_out, int out_size)
{
    (void)in_sizes; (void)n_in; (void)out_size;
    const float* X  = (const float*)d_in[0];
    const float* Wf = (const float*)d_in[1];
    const float* bf = (const float*)d_in[2];
    const float* Wi = (const float*)d_in[3];
    const float* bi = (const float*)d_in[4];
    const float* Wg = (const float*)d_in[5];
    const float* bg = (const float*)d_in[6];
    const float* Wo = (const float*)d_in[7];
    const float* bo = (const float*)d_in[8];
    float* out = (float*)d_out;

    dim3 g1(16, 1024);
    xproj_kernel<<<g1, 256>>>(X, Wf, Wi, Wg, Wo, bf, bi, bg, bo);

    lstm_seq_kernel<<<NBLK, NTHR>>>(Wf, Wi, Wg, Wo, out);
}

// round 15
// speedup vs baseline: 2.4706x; 2.4706x over previous
#include <cuda_runtime.h>
#include <math.h>
#include <stdint.h>

typedef unsigned long long ull;

#define SEQ   1024
#define BATCH 64
#define DH    256
#define DIN   256
#define NBLK  128
#define NTHR  256

// ---------------- device scratch (static allocs only) -----------------------
__device__ float    g_xq[(size_t)SEQ * 1024 * 64];   // [t][gatecol][b], 256MB
__device__ float    g_hbuf[2][DH * BATCH];           // double-buffered h, [unit][batch]
// counting flags: one per (step, producer-group of 16 CTAs), 128B apart
__device__ unsigned g_cflag[(SEQ + 1) * 8 * 32];

// ---------------- f32x2 packed helpers (Blackwell) --------------------------
__device__ __forceinline__ ull fma2(ull a, ull b, ull c) {
    ull d;
    asm("fma.rn.f32x2 %0, %1, %2, %3;" : "=l"(d) : "l"(a), "l"(b), "l"(c));
    return d;
}
__device__ __forceinline__ ull add2(ull a, ull b) {
    ull d;
    asm("add.rn.f32x2 %0, %1, %2;" : "=l"(d) : "l"(a), "l"(b));
    return d;
}
__device__ __forceinline__ ull pack2(float x, float y) {
    ull r;
    asm("mov.b64 %0, {%1, %2};" : "=l"(r) : "f"(x), "f"(y));
    return r;
}
__device__ __forceinline__ float2 unpack2(ull v) {
    float2 r;
    asm("mov.b64 {%0, %1}, %2;" : "=f"(r.x), "=f"(r.y) : "l"(v));
    return r;
}
__device__ __forceinline__ ulonglong2 ldcg_u2(const void* p) {
    ulonglong2 v;
    asm volatile("ld.global.cg.v2.u64 {%0, %1}, [%2];"
                 : "=l"(v.x), "=l"(v.y) : "l"(p));
    return v;
}
__device__ __forceinline__ unsigned ld_acq(const unsigned* p) {
    unsigned v;
    asm volatile("ld.acquire.gpu.global.u32 %0, [%1];" : "=r"(v) : "l"(p));
    return v;
}
__device__ __forceinline__ void red_rel(unsigned* p) {
    unsigned one = 1u;
    asm volatile("red.release.gpu.global.add.u32 [%0], %1;" :: "l"(p), "r"(one) : "memory");
}
// fast tanh: 1 - 2/(exp(2x)+1)  (monotone, correct at +-inf, err ~1e-6)
__device__ __forceinline__ float ftanh(float x) {
    float e = __expf(2.0f * x);
    return 1.0f - 2.0f / (e + 1.0f);
}
__device__ __forceinline__ float fsigmoid(float x) {
    return 1.0f / (1.0f + __expf(-x));
}

// ======================= Phase 1: X projection GEMM =========================
// g_xq[t, c, b] = sum_k X[t,b,k] * W_g[k, j] + bias_g[j],  c = g*256 + j
__global__ __launch_bounds__(256) void xproj_kernel(
    const float* __restrict__ X,
    const float* __restrict__ Wf, const float* __restrict__ Wi,
    const float* __restrict__ Wg, const float* __restrict__ Wo,
    const float* __restrict__ bf, const float* __restrict__ bi,
    const float* __restrict__ bg, const float* __restrict__ bo)
{
    __shared__ float As[16 * 68];   // [k][row]
    __shared__ float Bs[16 * 68];   // [k][col]

    const int t    = blockIdx.y;
    const int bx   = blockIdx.x;           // 0..15
    const int gsel = bx >> 2;
    const int j0   = (bx & 3) * 64;
    const float* W    = (gsel == 0) ? Wf : (gsel == 1) ? Wi : (gsel == 2) ? Wg : Wo;
    const float* bias = (gsel == 0) ? bf : (gsel == 1) ? bi : (gsel == 2) ? bg : bo;

    const int tx = threadIdx.x;

    // re-zero counting flags every replay (xproj completes before lstm starts)
    if (bx == 0) {
        if (tx < 8) g_cflag[((t << 3) + tx) << 5] = 0u;
        if (t == 0 && tx >= 8 && tx < 16) g_cflag[((SEQ << 3) + (tx - 8)) << 5] = 0u;
    }

    const int trow4 = (tx >> 4) * 4;
    const int tcol4 = (tx & 15) * 4;

    const int arow = tx >> 2;
    const int akq  = (tx & 3) * 4;
    const int bk   = tx >> 4;
    const int bc4  = (tx & 15) * 4;

    const float* Aptr = X + ((size_t)t * 64 + arow) * 256 + akq;
    const float* Bptr = W + (size_t)bk * 256 + j0 + bc4;

    ull acc[8];
    #pragma unroll
    for (int i = 0; i < 8; ++i) acc[i] = 0ull;

    float4 aReg = *(const float4*)Aptr;
    float4 bReg = *(const float4*)Bptr;

    for (int kt = 0; kt < 16; ++kt) {
        __syncthreads();
        As[(akq + 0) * 68 + arow] = aReg.x;
        As[(akq + 1) * 68 + arow] = aReg.y;
        As[(akq + 2) * 68 + arow] = aReg.z;
        As[(akq + 3) * 68 + arow] = aReg.w;
        *(float4*)&Bs[bk * 68 + bc4] = bReg;
        if (kt < 15) {
            aReg = *(const float4*)(Aptr + (kt + 1) * 16);
            bReg = *(const float4*)(Bptr + (size_t)(kt + 1) * 16 * 256);
        }
        __syncthreads();

        #pragma unroll
        for (int k = 0; k < 16; ++k) {
            float4 a4 = *(const float4*)&As[k * 68 + trow4];
            float4 b4 = *(const float4*)&Bs[k * 68 + tcol4];
            ull a01 = pack2(a4.x, a4.y);
            ull a23 = pack2(a4.z, a4.w);
            ull bb;
            bb = pack2(b4.x, b4.x); acc[0] = fma2(a01, bb, acc[0]); acc[1] = fma2(a23, bb, acc[1]);
            bb = pack2(b4.y, b4.y); acc[2] = fma2(a01, bb, acc[2]); acc[3] = fma2(a23, bb, acc[3]);
            bb = pack2(b4.z, b4.z); acc[4] = fma2(a01, bb, acc[4]); acc[5] = fma2(a23, bb, acc[5]);
            bb = pack2(b4.w, b4.w); acc[6] = fma2(a01, bb, acc[6]); acc[7] = fma2(a23, bb, acc[7]);
        }
    }

    #pragma unroll
    for (int jj = 0; jj < 4; ++jj) {
        float bv = bias[j0 + tcol4 + jj];
        float2 p01 = unpack2(acc[2 * jj]);
        float2 p23 = unpack2(acc[2 * jj + 1]);
        float4 outv = make_float4(p01.x + bv, p01.y + bv, p23.x + bv, p23.y + bv);
        size_t c = (size_t)bx * 64 + tcol4 + jj;
        *(float4*)&g_xq[(size_t)t * 65536 + c * 64 + trow4] = outv;
    }
}

// ======================= Phase 2: persistent recurrence =====================
// R4 skeleton: 128 CTAs x 256 thr, CTA owns 2 hidden units (8 gate-cols).
// K-split GEMM: thread = (bg 0..15: 4 batches) x (kc 0..15: 16 k), h via
// LDG.128. Warp 7 lanes 248..255 poll 8 group counters (==16); full sync;
// 16-deep smem partial reduce -> gate_s -> update by warps 0-1 with early
// release (bar.sync 1,64 -> red.release -> output stores). No trailing sync.
__global__ __launch_bounds__(NTHR, 1) void lstm_seq_kernel(
    const float* __restrict__ Wf, const float* __restrict__ Wi,
    const float* __restrict__ Wg, const float* __restrict__ Wo,
    float* __restrict__ out)
{
    extern __shared__ char smx[];
    ull* wh2    = (ull*)smx;          // [k][8 cols] dup pairs : 2048 ull (16KB)
    ull* pp     = wh2 + 2048;         // [16 kc][256]          : 4096 ull (32KB)
    ull* gate_s = pp + 4096;          // [8 cols][32 bpairs]   : 256 ull  (2KB)
    ull* c_s    = gate_s + 256;       // [2 units][32 bpairs]  : 64 ull

    const int tx = threadIdx.x;
    const int bx = blockIdx.x;
    const int u0 = bx << 1;            // first hidden unit owned
    const int bg = tx & 15;            // batch group (4 batches)
    const int kc = tx >> 4;            // k-chunk (16 k)

    // ---- load Wh slice, duplicated pairs: wh2[k*8 + c], c = g*2 + uu ----
    for (int idx = tx; idx < 2048; idx += NTHR) {
        int k = idx >> 3, c = idx & 7;
        const float* W = (c < 4) ? ((c < 2) ? Wf : Wi) : ((c < 6) ? Wg : Wo);
        float w = W[(size_t)(256 + k) * 256 + u0 + (c & 1)];
        wh2[idx] = pack2(w, w);
    }

    // ---- init h(0)=0, c=0, signal step-0 counter ----
    if (tx < 64) {
        c_s[tx] = 0ull;
        int u = tx >> 5, bp = tx & 31;
        *(ull*)&g_hbuf[0][(u0 + u) * 64 + (bp << 1)] = 0ull;
    }
    __syncthreads();
    if (tx == 0) red_rel(&g_cflag[(bx >> 4) << 5]);

    // reduce-role constants (thread tx -> col rc, batch-pair rbp)
    const int rc  = tx >> 5;
    const int rbp = tx & 31;
    const int rg  = rc >> 1;
    const size_t xq_off = (size_t)(rg * 256 + u0 + (rc & 1)) * 64 + (rbp << 1);

    float* outs = out;
    float* hxo  = out + (size_t)SEQ * 64 * 256;
    float* cxo  = hxo + 64 * 256;

    const ull* wpp = wh2 + kc * 128;          // w dup pairs for my k-chunk
    const int  hoff = kc * 16 * 64 + (bg << 2);

    for (int t = 0; t < SEQ; ++t) {
        // prefetch x-projection (independent of flags)
        ull xq = *(const ull*)&g_xq[(size_t)t * 65536 + xq_off];

        // wait for all 128 producers of h(t): warp-7 lanes poll 8 counters
        if (tx >= 248) {
            const unsigned* fp = &g_cflag[((t << 3) + (tx - 248)) << 5];
            while (ld_acq(fp) != 16u) { }
        }
        __syncthreads();

        // ---- K-split GEMM: acc[2c+p] over 16 k, h via LDG.128 ----
        const float* hb = g_hbuf[t & 1] + hoff;
        ull acc[16];
        #pragma unroll
        for (int i = 0; i < 16; ++i) acc[i] = 0ull;
        #pragma unroll
        for (int k = 0; k < 16; ++k) {
            ulonglong2 hh = ldcg_u2(hb + (k << 6));
            const ulonglong2* wv = (const ulonglong2*)(wpp + (k << 3));
            ulonglong2 w01 = wv[0], w23 = wv[1], w45 = wv[2], w67 = wv[3];
            acc[0]  = fma2(hh.x, w01.x, acc[0]);  acc[1]  = fma2(hh.y, w01.x, acc[1]);
            acc[2]  = fma2(hh.x, w01.y, acc[2]);  acc[3]  = fma2(hh.y, w01.y, acc[3]);
            acc[4]  = fma2(hh.x, w23.x, acc[4]);  acc[5]  = fma2(hh.y, w23.x, acc[5]);
            acc[6]  = fma2(hh.x, w23.y, acc[6]);  acc[7]  = fma2(hh.y, w23.y, acc[7]);
            acc[8]  = fma2(hh.x, w45.x, acc[8]);  acc[9]  = fma2(hh.y, w45.x, acc[9]);
            acc[10] = fma2(hh.x, w45.y, acc[10]); acc[11] = fma2(hh.y, w45.y, acc[11]);
            acc[12] = fma2(hh.x, w67.x, acc[12]); acc[13] = fma2(hh.y, w67.x, acc[13]);
            acc[14] = fma2(hh.x, w67.y, acc[14]); acc[15] = fma2(hh.y, w67.y, acc[15]);
        }
        // store partials: pp[kc][c*32 + 2bg + p]
        {
            ull* pdst = pp + kc * 256 + (bg << 1);
            #pragma unroll
            for (int c = 0; c < 8; ++c) {
                pdst[(c << 5)    ] = acc[2 * c];
                pdst[(c << 5) + 1] = acc[2 * c + 1];
            }
        }
        __syncthreads();

        // ---- reduce 16 partials (tree, f32x2 adds), + xq, activation ----
        ull s0 = add2(pp[tx],        pp[tx + 256]);
        ull s1 = add2(pp[tx + 512],  pp[tx + 768]);
        ull s2 = add2(pp[tx + 1024], pp[tx + 1280]);
        ull s3 = add2(pp[tx + 1536], pp[tx + 1792]);
        ull s4 = add2(pp[tx + 2048], pp[tx + 2304]);
        ull s5 = add2(pp[tx + 2560], pp[tx + 2816]);
        ull s6 = add2(pp[tx + 3072], pp[tx + 3328]);
        ull s7 = add2(pp[tx + 3584], pp[tx + 3840]);
        s0 = add2(s0, s1); s2 = add2(s2, s3); s4 = add2(s4, s5); s6 = add2(s6, s7);
        s0 = add2(s0, s2); s4 = add2(s4, s6);
        ull s = add2(add2(s0, s4), xq);

        float2 v = unpack2(s);
        float2 a;
        if (rg == 2) { a.x = ftanh(v.x);    a.y = ftanh(v.y); }
        else         { a.x = fsigmoid(v.x); a.y = fsigmoid(v.y); }
        gate_s[tx] = pack2(a.x, a.y);
        __syncthreads();

        // ---- state update (warps 0-1); early release, then output stores ----
        if (tx < 64) {
            int u = tx >> 5, bp = tx & 31;
            float2 f  = unpack2(gate_s[tx]);
            float2 ii = unpack2(gate_s[64 + tx]);
            float2 gg = unpack2(gate_s[128 + tx]);
            float2 oo = unpack2(gate_s[192 + tx]);
            float2 co = unpack2(c_s[tx]);
            float c0 = f.x * co.x + ii.x * gg.x;
            float c1 = f.y * co.y + ii.y * gg.y;
            c_s[tx] = pack2(c0, c1);
            float h0 = oo.x * ftanh(c0);
            float h1 = oo.y * ftanh(c1);
            int j = u0 + u;
            int b = bp << 1;
            *(ull*)&g_hbuf[(t + 1) & 1][j * 64 + b] = pack2(h0, h1);
            asm volatile("bar.sync 1, 64;" ::: "memory");   // warps 0-1 only
            if (tx == 0) red_rel(&g_cflag[(((t + 1) << 3) + (bx >> 4)) << 5]);
            outs[((size_t)t * 64 + b) * 256 + j]     = h0;
            outs[((size_t)t * 64 + b + 1) * 256 + j] = h1;
            if (t == SEQ - 1) {
                hxo[b * 256 + j] = h0; hxo[(b + 1) * 256 + j] = h1;
                cxo[b * 256 + j] = c0; cxo[(b + 1) * 256 + j] = c1;
            }
        }
        // no trailing sync: loop-top sync#1 (after poll) provides the barrier;
        // release happens before sync#1 -> no deadlock.
    }
}

// ============================== launch ======================================
extern "C" void kernel_launch(void* const* d_in, const int* in_sizes, int n_in,
                              void* d_out, int out_size)
{
    (void)in_sizes; (void)n_in; (void)out_size;
    const float* X  = (const float*)d_in[0];
    const float* Wf = (const float*)d_in[1];
    const float* bf = (const float*)d_in[2];
    const float* Wi = (const float*)d_in[3];
    const float* bi = (const float*)d_in[4];
    const float* Wg = (const float*)d_in[5];
    const float* bg = (const float*)d_in[6];
    const float* Wo = (const float*)d_in[7];
    const float* bo = (const float*)d_in[8];
    float* out = (float*)d_out;

    dim3 g1(16, 1024);
    xproj_kernel<<<g1, 256>>>(X, Wf, Wi, Wg, Wo, bf, bi, bg, bo);

    const int smem2 = 6464 * 8;   // 51,712 B
    cudaFuncSetAttribute(lstm_seq_kernel,
                         cudaFuncAttributeMaxDynamicSharedMemorySize, smem2);
    lstm_seq_kernel<<<NBLK, NTHR, smem2>>>(Wf, Wi, Wg, Wo, out);
}